// round 13
// baseline (speedup 1.0000x reference)
#include <cuda_runtime.h>
#include <cuda_fp16.h>
#include <cuda_bf16.h>
#include <math.h>

// ---------------- problem constants ------------------------------------------
#define NQ      64
#define KDIM    768
#define TILE_M  128                 // bank rows per CTA tile
#define CHUNK_K 64                  // fp32 k-elems per chunk
#define NCHUNK  (KDIM / CHUNK_K)    // 12
#define MAXROWS 500000
#define NSEG    8                   // top-k segments per query
#define SEGK    16                  // candidates kept per (q, segment)
#define CAND    16                  // candidates exactly rescored per query
#define TB_PAD  136                 // transpose buffer row pitch (bf16 elems)
#define NTHREADS 256

// ---------------- smem layout (score kernel) ---------------------------------
#define SM_INVN 0                                   // float[128]
#define SM_Q    1024                                // 768 k x 32 qpair x 4 B = 98304
#define SM_BT0  (SM_Q + KDIM * 32 * 4)              // 99328: B rpair buf 0 (16 KB)
#define SM_BT1  (SM_BT0 + 64 * 64 * 4)              // 115712: B rpair buf 1 (16 KB)
#define SCORE_SMEM (SM_BT1 + 64 * 64 * 4)           // 132096

// ---------------- device scratch (allocation-free rule) ----------------------
__device__ __align__(16) float    g_qn  [NQ * KDIM];          // fp32 normalized queries
__device__ __align__(16) unsigned g_qph [KDIM * 32];          // half2 (q2j,q2j+1) [k][qpair]
__device__ __align__(16) __nv_bfloat16 g_simsb[(size_t)NQ * MAXROWS]; // 64 MB bf16 sims
__device__ float g_segv[NQ * NSEG * SEGK];
__device__ int   g_segi[NQ * NSEG * SEGK];

// ---------------- kernel 1: normalize queries + transposed half2-pair copy ---
__global__ void norm_q_kernel(const float* __restrict__ q) {
    __shared__ float red[256];
    __shared__ float sinv[NQ];
    const int tid = threadIdx.x;
    const int qi = tid >> 2, t4 = tid & 3;          // 4 threads per query
    const float4* qr = (const float4*)(q + qi * KDIM + t4 * 192);
    float ss = 0.f;
    #pragma unroll
    for (int i = 0; i < 48; i++) {
        float4 v = qr[i];
        ss += v.x * v.x + v.y * v.y + v.z * v.z + v.w * v.w;
    }
    red[tid] = ss;
    __syncthreads();
    if (t4 == 0) {
        float tot = red[qi * 4] + red[qi * 4 + 1] + red[qi * 4 + 2] + red[qi * 4 + 3];
        sinv[qi] = 1.0f / fmaxf(sqrtf(tot), 1e-12f);
    }
    __syncthreads();
    {
        const float inv = sinv[qi];
        float4* dst = (float4*)(g_qn + qi * KDIM + t4 * 192);
        #pragma unroll
        for (int i = 0; i < 48; i++) {
            float4 v = qr[i];
            dst[i] = make_float4(v.x * inv, v.y * inv, v.z * inv, v.w * inv);
        }
    }
    // transposed half2 pairs: g_qph[k*32 + qp] = (qn[2qp][k], qn[2qp+1][k])
    for (int i = tid; i < KDIM * 32; i += 256) {
        const int k = i >> 5, qp = i & 31;
        float a = q[(2 * qp    ) * KDIM + k] * sinv[2 * qp    ];
        float b = q[(2 * qp + 1) * KDIM + k] * sinv[2 * qp + 1];
        __half2 h = __floats2half2_rn(a, b);
        g_qph[i] = *(unsigned*)&h;
    }
}

// ---------------- kernel 2: HFMA2 half2 GEMM score ---------------------------
__device__ __forceinline__ void ld_chunk(float4 (&f)[8], const float* const (&rp)[8],
                                         const bool (&vld)[8], int c) {
    #pragma unroll
    for (int p = 0; p < 8; p++) {
        if (vld[p]) f[p] = *(const float4*)(rp[p] + c * CHUNK_K);
        else        f[p] = make_float4(0.f, 0.f, 0.f, 0.f);
    }
}

__global__ __launch_bounds__(NTHREADS, 1)
void score_kernel(const float* __restrict__ bank, int nrows) {
    extern __shared__ char smem[];
    float*    invn = (float*)(smem + SM_INVN);
    unsigned* Qs   = (unsigned*)(smem + SM_Q);
    const int tid = threadIdx.x, warp = tid >> 5, lane = tid & 31;
    const int lr = lane >> 4, lc = lane & 15;

    // ---- gmem staging mapping: 16 lanes per row, line-contiguous LDG.128 -----
    int rloc[8]; const float* rp[8]; bool vld[8]; float ssq[8];
    #pragma unroll
    for (int p = 0; p < 8; p++) {
        int r = p * 16 + warp * 2 + lr;
        rloc[p] = r;
        long long grow = (long long)blockIdx.x * TILE_M + r;
        vld[p] = grow < (long long)nrows;
        rp[p]  = bank + grow * (long long)KDIM + lc * 4;
        ssq[p] = 0.f;
    }
    const int kb  = lc * 4;              // chunk-k base this lane stages
    const unsigned ssw = (unsigned)warp << 2;  // staging swizzle (rpair&7 == warp)

    // ---- stage ALL query half2 pairs once (96 KB, L2-resident source) --------
    for (int i = tid; i < KDIM * 32 / 4; i += NTHREADS)
        ((uint4*)Qs)[i] = ((const uint4*)g_qph)[i];

    // ---- compute mapping: 2 rpairs x 4 qpairs per thread ----------------------
    const int rg = tid >> 3;             // 0..31 rpair-group (2 rpairs each)
    const int qg = tid & 7;              // 0..7 qpair-group (4 qpairs each)
    const int rpA = rg * 2, rpB = rg * 2 + 1;
    const unsigned swA = (unsigned)(rpA & 7) << 2;
    const unsigned swB = (unsigned)(rpB & 7) << 2;

    __half2 hacc[16];                    // [row 0..3][qpair 0..3]
    float   facc[32];                    // [row 0..3][q 0..7]
    const __half2 hz = __float2half2_rn(0.f);
    #pragma unroll
    for (int i = 0; i < 16; i++) hacc[i] = hz;
    #pragma unroll
    for (int i = 0; i < 32; i++) facc[i] = 0.f;

    float4 f[8];
    ld_chunk(f, rp, vld, 0);             // prologue

    #pragma unroll 1
    for (int c = 0; c < NCHUNK; c++) {
        unsigned* BT = (unsigned*)(smem + ((c & 1) ? SM_BT1 : SM_BT0));
        // ---- stage chunk: convert + pair rows via shuffle + swizzled STS ------
        #pragma unroll
        for (int p = 0; p < 8; p++) {
            float4 fv = f[p];
            ssq[p] += fv.x * fv.x + fv.y * fv.y + fv.z * fv.z + fv.w * fv.w;
            __half2 h01 = __floats2half2_rn(fv.x, fv.y);
            __half2 h23 = __floats2half2_rn(fv.z, fv.w);
            unsigned u01 = *(unsigned*)&h01, u23 = *(unsigned*)&h23;
            unsigned pu01 = __shfl_xor_sync(0xffffffffu, u01, 16);
            unsigned pu23 = __shfl_xor_sync(0xffffffffu, u23, 16);
            unsigned* BTw = BT + (p * 8 + warp) * 64;
            if (lr == 0) {   // own = even row, partner = odd row
                BTw[(kb + 0) ^ ssw] = __byte_perm(u01, pu01, 0x5410);
                BTw[(kb + 1) ^ ssw] = __byte_perm(u01, pu01, 0x7632);
            } else {         // own = odd row, partner = even row
                BTw[(kb + 2) ^ ssw] = __byte_perm(pu23, u23, 0x5410);
                BTw[(kb + 3) ^ ssw] = __byte_perm(pu23, u23, 0x7632);
            }
        }
        __syncthreads();     // single sync per chunk (double-buffer safe: see R12)

        // prefetch next chunk's gmem loads before compute
        if (c + 1 < NCHUNK) ld_chunk(f, rp, vld, c + 1);

        // ---- HFMA2 GEMM over 64 k ---------------------------------------------
        const unsigned* BA = BT + rpA * 64;
        const unsigned* BB = BT + rpB * 64;
        const unsigned* Qc = Qs + c * (CHUNK_K * 32) + qg * 4;
        #pragma unroll 8
        for (int k = 0; k < CHUNK_K; k++) {
            unsigned wa = BA[k ^ swA];
            unsigned wb = BB[k ^ swB];
            uint4 qv = *(const uint4*)(Qc + k * 32);
            unsigned d0 = __byte_perm(wa, wa, 0x1010);   // (even,even)
            unsigned d1 = __byte_perm(wa, wa, 0x3232);   // (odd,odd)
            unsigned d2 = __byte_perm(wb, wb, 0x1010);
            unsigned d3 = __byte_perm(wb, wb, 0x3232);
            __half2 hd0 = *(__half2*)&d0, hd1 = *(__half2*)&d1;
            __half2 hd2 = *(__half2*)&d2, hd3 = *(__half2*)&d3;
            __half2 q0 = *(__half2*)&qv.x, q1 = *(__half2*)&qv.y;
            __half2 q2 = *(__half2*)&qv.z, q3 = *(__half2*)&qv.w;
            hacc[0]  = __hfma2(hd0, q0, hacc[0]);
            hacc[1]  = __hfma2(hd0, q1, hacc[1]);
            hacc[2]  = __hfma2(hd0, q2, hacc[2]);
            hacc[3]  = __hfma2(hd0, q3, hacc[3]);
            hacc[4]  = __hfma2(hd1, q0, hacc[4]);
            hacc[5]  = __hfma2(hd1, q1, hacc[5]);
            hacc[6]  = __hfma2(hd1, q2, hacc[6]);
            hacc[7]  = __hfma2(hd1, q3, hacc[7]);
            hacc[8]  = __hfma2(hd2, q0, hacc[8]);
            hacc[9]  = __hfma2(hd2, q1, hacc[9]);
            hacc[10] = __hfma2(hd2, q2, hacc[10]);
            hacc[11] = __hfma2(hd2, q3, hacc[11]);
            hacc[12] = __hfma2(hd3, q0, hacc[12]);
            hacc[13] = __hfma2(hd3, q1, hacc[13]);
            hacc[14] = __hfma2(hd3, q2, hacc[14]);
            hacc[15] = __hfma2(hd3, q3, hacc[15]);
        }
        // fold half accumulators into fp32 every 2 chunks (bounds walk error)
        if (c & 1) {
            #pragma unroll
            for (int r4 = 0; r4 < 4; r4++)
                #pragma unroll
                for (int j = 0; j < 4; j++) {
                    float2 f2 = __half22float2(hacc[r4 * 4 + j]);
                    facc[r4 * 8 + j * 2    ] += f2.x;
                    facc[r4 * 8 + j * 2 + 1] += f2.y;
                    hacc[r4 * 4 + j] = hz;
                }
        }
    }

    // ---- row inverse norms (16 lanes share a row) -----------------------------
    #pragma unroll
    for (int p = 0; p < 8; p++) {
        float s = ssq[p];
        s += __shfl_xor_sync(0xffffffffu, s, 1);
        s += __shfl_xor_sync(0xffffffffu, s, 2);
        s += __shfl_xor_sync(0xffffffffu, s, 4);
        s += __shfl_xor_sync(0xffffffffu, s, 8);
        if (lc == 0) invn[rloc[p]] = 1.0f / fmaxf(sqrtf(s), 1e-12f);
    }
    __syncthreads();

    // ---- epilogue 1: facc -> smem transpose buffer [q][TB_PAD] bf16 -----------
    {
        __nv_bfloat16* tb = (__nv_bfloat16*)(smem + SM_BT0);
        const int r0 = rg * 4;
        const float i0 = invn[r0], i1 = invn[r0 + 1];
        const float i2 = invn[r0 + 2], i3 = invn[r0 + 3];
        #pragma unroll
        for (int l = 0; l < 8; l++) {
            const int q = qg * 8 + l;
            __nv_bfloat162 a = __floats2bfloat162_rn(facc[0 * 8 + l] * i0,
                                                     facc[1 * 8 + l] * i1);
            __nv_bfloat162 b = __floats2bfloat162_rn(facc[2 * 8 + l] * i2,
                                                     facc[3 * 8 + l] * i3);
            *(__nv_bfloat162*)&tb[q * TB_PAD + r0    ] = a;
            *(__nv_bfloat162*)&tb[q * TB_PAD + r0 + 2] = b;
        }
    }
    __syncthreads();

    // ---- epilogue 2: coalesced vectorized sims store --------------------------
    {
        const int q = tid >> 2, seg = tid & 3;
        const long long tb0 = (long long)blockIdx.x * TILE_M;
        const __nv_bfloat16* tb = (const __nv_bfloat16*)(smem + SM_BT0);
        __nv_bfloat16* dst = g_simsb + (size_t)q * nrows;
        if ((nrows & 7) == 0) {
            #pragma unroll
            for (int i = 0; i < 4; i++) {
                long long g0 = tb0 + seg * 32 + i * 8;
                if (g0 + 8 <= (long long)nrows) {
                    uint4 v = *(const uint4*)(smem + SM_BT0 + q * (TB_PAD * 2) + seg * 64 + i * 16);
                    *(uint4*)(dst + g0) = v;
                } else {
                    for (int e = 0; e < 8 && g0 + e < (long long)nrows; e++)
                        dst[g0 + e] = tb[q * TB_PAD + seg * 32 + i * 8 + e];
                }
            }
        } else {
            for (int i = 0; i < 32; i++) {
                long long g0 = tb0 + seg * 32 + i;
                if (g0 < (long long)nrows) dst[g0] = tb[q * TB_PAD + seg * 32 + i];
            }
        }
    }
}

// ---------------- kernel 3: segmented top-16 screening -----------------------
__device__ __forceinline__ void tk_insert(float (&v)[SEGK], int (&id)[SEGK],
                                          float nv, int ni) {
    if (nv <= v[SEGK - 1]) return;
    int j = SEGK - 1;
    while (j > 0 && nv > v[j - 1]) { v[j] = v[j - 1]; id[j] = id[j - 1]; j--; }
    v[j] = nv; id[j] = ni;
}

__global__ __launch_bounds__(256, 1) void topk_kernel(int nrows) {
    __shared__ float sv[256 * SEGK];
    __shared__ int   si[256 * SEGK];
    const int seg = blockIdx.x, q = blockIdx.y, tid = threadIdx.x;
    const int len  = ((nrows + NSEG - 1) / NSEG + 3) & ~3;
    const int base = seg * len;
    const int end  = min(base + len, nrows);
    const __nv_bfloat16* s = g_simsb + (size_t)q * nrows;

    float vals[SEGK]; int ids[SEGK];
    #pragma unroll
    for (int i = 0; i < SEGK; i++) { vals[i] = -3.4e38f; ids[i] = 0x7fffffff; }

    if ((nrows & 3) == 0 && base < end) {
        const uint2* s4 = (const uint2*)s;
        for (int i = (base >> 2) + tid; i < (end >> 2); i += 256) {
            uint2 u = s4[i];
            __nv_bfloat162 p0 = *(__nv_bfloat162*)&u.x;
            __nv_bfloat162 p1 = *(__nv_bfloat162*)&u.y;
            int bi = i << 2;
            tk_insert(vals, ids, __low2float(p0),  bi);
            tk_insert(vals, ids, __high2float(p0), bi + 1);
            tk_insert(vals, ids, __low2float(p1),  bi + 2);
            tk_insert(vals, ids, __high2float(p1), bi + 3);
        }
    } else {
        for (int i = base + tid; i < end; i += 256)
            tk_insert(vals, ids, __bfloat162float(s[i]), i);
    }

    #pragma unroll
    for (int i = 0; i < SEGK; i++) { sv[tid * SEGK + i] = vals[i]; si[tid * SEGK + i] = ids[i]; }
    __syncthreads();

    for (int st = 128; st > 0; st >>= 1) {
        if (tid < st) {
            const int ao = tid * SEGK, bo = (tid + st) * SEGK;
            float ov[SEGK]; int oi[SEGK];
            int ia = 0, ib = 0;
            #pragma unroll
            for (int o = 0; o < SEGK; o++) {
                float va = (ia < SEGK) ? sv[ao + ia] : -3.4e38f;
                float vb = (ib < SEGK) ? sv[bo + ib] : -3.4e38f;
                bool takeA;
                if (va > vb) takeA = true;
                else if (va < vb) takeA = false;
                else takeA = (si[ao + min(ia, SEGK - 1)] <= si[bo + min(ib, SEGK - 1)]);
                if (takeA) { ov[o] = va; oi[o] = si[ao + min(ia, SEGK - 1)]; ia++; }
                else       { ov[o] = vb; oi[o] = si[bo + min(ib, SEGK - 1)]; ib++; }
            }
            #pragma unroll
            for (int o = 0; o < SEGK; o++) { sv[ao + o] = ov[o]; si[ao + o] = oi[o]; }
        }
        __syncthreads();
    }

    if (tid == 0) {
        #pragma unroll
        for (int i = 0; i < SEGK; i++) {
            g_segv[(q * NSEG + seg) * SEGK + i] = sv[i];
            g_segi[(q * NSEG + seg) * SEGK + i] = si[i];
        }
    }
}

// ---------------- kernel 4: merge + exact fp32 rescore + final top-k ---------
__global__ __launch_bounds__(256, 1)
void final_kernel(const float* __restrict__ bank, float* __restrict__ out,
                  int nrows, int k) {
    __shared__ float cv[NSEG * SEGK];
    __shared__ int   ci[NSEG * SEGK];
    __shared__ float sv[CAND];
    __shared__ int   sid[CAND];
    __shared__ float rv[CAND];
    const int q = blockIdx.x, tid = threadIdx.x;
    const int lane = tid & 31, warp = tid >> 5;

    if (tid < NSEG * SEGK) {
        cv[tid] = g_segv[q * NSEG * SEGK + tid];
        ci[tid] = g_segi[q * NSEG * SEGK + tid];
    }
    __syncthreads();

    if (tid == 0) {
        float bv[CAND]; int bi[CAND];
        #pragma unroll
        for (int i = 0; i < CAND; i++) { bv[i] = -3.4e38f; bi[i] = 0x7fffffff; }
        for (int i = 0; i < NSEG * SEGK; i++) {
            float v = cv[i]; int id = ci[i];
            float lv = bv[CAND - 1]; int li = bi[CAND - 1];
            if (v < lv || (v == lv && id >= li)) continue;
            int j = CAND - 1;
            while (j > 0 && (v > bv[j - 1] || (v == bv[j - 1] && id < bi[j - 1]))) {
                bv[j] = bv[j - 1]; bi[j] = bi[j - 1]; j--;
            }
            bv[j] = v; bi[j] = id;
        }
        #pragma unroll
        for (int i = 0; i < CAND; i++) { sv[i] = bv[i]; sid[i] = bi[i]; }
    }
    __syncthreads();

    for (int c = warp; c < CAND; c += 8) {
        const int id = sid[c];
        float val = -3.4e38f;
        if (id < nrows) {
            const float4* b4 = (const float4*)(bank + (long long)id * KDIM);
            const float4* q4 = (const float4*)(g_qn + q * KDIM);
            float dot = 0.f, ss = 0.f;
            #pragma unroll
            for (int i = 0; i < 6; i++) {
                float4 bb = b4[lane + i * 32];
                float4 qq = q4[lane + i * 32];
                dot = fmaf(qq.x, bb.x, fmaf(qq.y, bb.y, fmaf(qq.z, bb.z, fmaf(qq.w, bb.w, dot))));
                ss  = fmaf(bb.x, bb.x, fmaf(bb.y, bb.y, fmaf(bb.z, bb.z, fmaf(bb.w, bb.w, ss))));
            }
            #pragma unroll
            for (int o = 16; o; o >>= 1) {
                dot += __shfl_xor_sync(0xffffffffu, dot, o);
                ss  += __shfl_xor_sync(0xffffffffu, ss,  o);
            }
            val = dot / fmaxf(sqrtf(ss), 1e-12f);
        }
        if (lane == 0) rv[c] = val;
    }
    __syncthreads();

    if (tid == 0) {
        bool used[CAND];
        #pragma unroll
        for (int i = 0; i < CAND; i++) used[i] = false;
        for (int j = 0; j < k; j++) {
            int best = -1; float bvv = -3.4e38f;
            for (int i = 0; i < CAND; i++) {
                if (used[i]) continue;
                if (best < 0 || rv[i] > bvv ||
                    (rv[i] == bvv && sid[i] < sid[best])) { bvv = rv[i]; best = i; }
            }
            used[best] = true;
            out[q * k + j]          = bvv;
            out[NQ * k + q * k + j] = (float)sid[best];
        }
    }
}

// ---------------- launch -----------------------------------------------------
extern "C" void kernel_launch(void* const* d_in, const int* in_sizes, int n_in,
                              void* d_out, int out_size) {
    const float* query = (const float*)d_in[0];
    const float* bank  = (const float*)d_in[1];
    const int nrows = in_sizes[1] / KDIM;
    const int k = out_size / (2 * NQ);

    cudaFuncSetAttribute(score_kernel, cudaFuncAttributeMaxDynamicSharedMemorySize, SCORE_SMEM);

    norm_q_kernel<<<1, 256>>>(query);

    const int ntiles = (nrows + TILE_M - 1) / TILE_M;
    score_kernel<<<ntiles, NTHREADS, SCORE_SMEM>>>(bank, nrows);

    topk_kernel<<<dim3(NSEG, NQ), 256>>>(nrows);

    final_kernel<<<NQ, 256>>>(bank, (float*)d_out, nrows, k);
}

// round 14
// speedup vs baseline: 2.9835x; 2.9835x over previous
#include <cuda_runtime.h>
#include <cuda_bf16.h>
#include <math.h>

// ---------------- problem constants ------------------------------------------
#define NQ      64
#define KDIM    768
#define TILE_M  128                 // bank rows per CTA tile
#define CHUNK_K 64                  // K elems per chunk (bf16 row = 128 B)
#define NCHUNK  (KDIM / CHUNK_K)    // 12
#define MAXROWS 500000
#define MAXTILES ((MAXROWS + TILE_M - 1) / TILE_M)   // 3907
#define TPT     4                   // candidates kept per (q, tile)
#define CAND    16                  // candidates exactly rescored per query
#define TB_PAD  136                 // transpose buffer row pitch (bf16 elems)

// ---------------- smem layout (score kernel) ---------------------------------
#define SM_INVN 0                                   // float[128]
#define SM_Q    1024                                // 12 chunks x 64 q x 128 B = 98304
#define SM_B0   (SM_Q + NCHUNK * 64 * 128)          // 99328: B buf 0 (16 KB)
#define SM_B1   (SM_B0 + TILE_M * 128)              // 115712: B buf 1 (16 KB)
#define SM_CV   (SM_B1 + 2048)                      // float[256*4] (tb ends at SM_B1+1024)
#define SM_CI   (SM_CV + 4096)                      // int[256*4]
#define SCORE_SMEM (SM_B1 + TILE_M * 128)           // 132096

// ---------------- device scratch (allocation-free rule) ----------------------
__device__ __align__(16) float         g_qn [NQ * KDIM];              // fp32 normalized queries
__device__ __align__(16) __nv_bfloat16 g_qnb[NQ * KDIM];              // bf16 copy
__device__ __align__(16) float g_ctv[(size_t)NQ * MAXTILES * TPT];    // per-tile cand vals
__device__ __align__(16) int   g_cti[(size_t)NQ * MAXTILES * TPT];    // per-tile cand ids

// ---------------- kernel 1: normalize queries --------------------------------
__global__ void norm_q_kernel(const float* __restrict__ q) {
    __shared__ float red[256];
    int qi = blockIdx.x, tid = threadIdx.x;
    const float* qr = q + qi * KDIM;
    float v0 = qr[tid], v1 = qr[tid + 256], v2 = qr[tid + 512];
    red[tid] = v0 * v0 + v1 * v1 + v2 * v2;
    __syncthreads();
    for (int st = 128; st > 0; st >>= 1) {
        if (tid < st) red[tid] += red[tid + st];
        __syncthreads();
    }
    float inv = 1.0f / fmaxf(sqrtf(red[0]), 1e-12f);
    float o0 = v0 * inv, o1 = v1 * inv, o2 = v2 * inv;
    g_qn[qi * KDIM + tid      ] = o0;
    g_qn[qi * KDIM + tid + 256] = o1;
    g_qn[qi * KDIM + tid + 512] = o2;
    g_qnb[qi * KDIM + tid      ] = __float2bfloat16(o0);
    g_qnb[qi * KDIM + tid + 256] = __float2bfloat16(o1);
    g_qnb[qi * KDIM + tid + 512] = __float2bfloat16(o2);
}

// ---------------- kernel 2: mma.sync score + fused per-tile top-4 ------------
__device__ __forceinline__ void ld_chunk(float4 (&f)[8], const float* const (&rp)[8],
                                         const bool (&vld)[8], int c) {
    #pragma unroll
    for (int p = 0; p < 8; p++) {
        if (vld[p]) f[p] = *(const float4*)(rp[p] + c * CHUNK_K);
        else        f[p] = make_float4(0.f, 0.f, 0.f, 0.f);
    }
}

__device__ __forceinline__ void ldsm_x4(unsigned& r0, unsigned& r1, unsigned& r2,
                                        unsigned& r3, unsigned addr) {
    asm volatile("ldmatrix.sync.aligned.m8n8.x4.shared.b16 {%0,%1,%2,%3}, [%4];"
                 : "=r"(r0), "=r"(r1), "=r"(r2), "=r"(r3) : "r"(addr));
}

__device__ __forceinline__ unsigned s2u(const void* p) {
    unsigned a;
    asm("{ .reg .u64 t; cvta.to.shared.u64 t, %1; cvt.u32.u64 %0, t; }" : "=r"(a) : "l"(p));
    return a;
}

__global__ __launch_bounds__(256, 1)
void score_kernel(const float* __restrict__ bank, int nrows) {
    extern __shared__ char smem[];
    const unsigned sbase = s2u(smem);
    const int tid = threadIdx.x, warp = tid >> 5, lane = tid & 31;
    const int lr = lane >> 4, lc = lane & 15;

    // ---- global load mapping: 16 lanes per row, line-contiguous LDG.128 ------
    int rloc[8]; const float* rp[8]; bool vld[8]; float ssq[8];
    #pragma unroll
    for (int p = 0; p < 8; p++) {
        int r = p * 16 + warp * 2 + lr;
        rloc[p] = r;
        long long grow = (long long)blockIdx.x * TILE_M + r;
        vld[p] = grow < (long long)nrows;
        rp[p]  = bank + grow * (long long)KDIM + lc * 4;
        ssq[p] = 0.f;
    }
    const int scol = (lc * 8) ^ (((warp * 2 + lr) & 7) << 4);  // row&7 is p-invariant

    // ---- stage all queries: [chunk][64 q][128 B], XOR-swizzled ----------------
    for (int i = tid; i < NQ * KDIM / 4; i += 256) {
        int qi  = i / 192;
        int rem = i - qi * 192;
        int c   = rem >> 4;
        int k4  = rem & 15;
        uint2 v = ((const uint2*)g_qnb)[i];
        *(uint2*)(smem + SM_Q + c * 8192 + qi * 128 + ((k4 * 8) ^ ((qi & 7) << 4))) = v;
    }

    // ---- mma thread constants (R8-proven layout) ------------------------------
    const int qbase = (warp & 3) * 16;          // m (query) strip
    const int nbase = (warp >> 2) * 64;         // n (bank row) strip
    const int arow  = qbase + ((lane >> 3) & 1) * 8 + (lane & 7);
    const int axtr  = (lane >> 4) * 16;
    const int brow0 = nbase + ((lane >> 4) & 1) * 8 + (lane & 7);   // + pair*16
    const int bxtr  = ((lane >> 3) & 1) * 16;
    const int lsw   = (lane & 7) << 4;

    float acc[8][4];
    #pragma unroll
    for (int i = 0; i < 8; i++)
        #pragma unroll
        for (int j = 0; j < 4; j++) acc[i][j] = 0.f;

    float4 f[8];
    ld_chunk(f, rp, vld, 0);           // prologue: chunk 0 in flight

    for (int c = 0; c < NCHUNK; c++) {
        const unsigned bb = sbase + ((c & 1) ? SM_B1 : SM_B0);
        // convert + STS chunk c into buffer c&1 (waits on its LDGs via scoreboard)
        #pragma unroll
        for (int p = 0; p < 8; p++) {
            float4 fv = f[p];
            ssq[p] += fv.x * fv.x + fv.y * fv.y + fv.z * fv.z + fv.w * fv.w;
            __nv_bfloat162 p0 = __floats2bfloat162_rn(fv.x, fv.y);
            __nv_bfloat162 p1 = __floats2bfloat162_rn(fv.z, fv.w);
            uint2 u;
            u.x = *(unsigned*)&p0;
            u.y = *(unsigned*)&p1;
            *(uint2*)(smem + ((c & 1) ? SM_B1 : SM_B0) + rloc[p] * 128 + scol) = u;
        }
        __syncthreads();   // single sync: STS(c) visible; double-buffer makes the
                           // fast-warp STS(c+1) (other buffer) safe vs mma(c).

        // next chunk's loads issued before mma work (latency hidden behind mma)
        if (c + 1 < NCHUNK) ld_chunk(f, rp, vld, c + 1);

        // mma over chunk c: 4 k16 steps x 8 ntiles
        const unsigned qb = sbase + SM_Q + c * 8192;
        #pragma unroll
        for (int kk = 0; kk < 4; kk++) {
            unsigned a0, a1, a2, a3;
            ldsm_x4(a0, a1, a2, a3,
                    qb + arow * 128 + ((kk * 32 + axtr) ^ lsw));
            #pragma unroll
            for (int pair = 0; pair < 4; pair++) {
                unsigned b0, b1, b2, b3;
                ldsm_x4(b0, b1, b2, b3,
                        bb + (brow0 + pair * 16) * 128 + ((kk * 32 + bxtr) ^ lsw));
                asm volatile(
                    "mma.sync.aligned.m16n8k16.row.col.f32.bf16.bf16.f32 "
                    "{%0,%1,%2,%3}, {%4,%5,%6,%7}, {%8,%9}, {%0,%1,%2,%3};\n"
                    : "+f"(acc[pair*2][0]), "+f"(acc[pair*2][1]),
                      "+f"(acc[pair*2][2]), "+f"(acc[pair*2][3])
                    : "r"(a0), "r"(a1), "r"(a2), "r"(a3), "r"(b0), "r"(b1));
                asm volatile(
                    "mma.sync.aligned.m16n8k16.row.col.f32.bf16.bf16.f32 "
                    "{%0,%1,%2,%3}, {%4,%5,%6,%7}, {%8,%9}, {%0,%1,%2,%3};\n"
                    : "+f"(acc[pair*2+1][0]), "+f"(acc[pair*2+1][1]),
                      "+f"(acc[pair*2+1][2]), "+f"(acc[pair*2+1][3])
                    : "r"(a0), "r"(a1), "r"(a2), "r"(a3), "r"(b2), "r"(b3));
            }
        }
    }

    // ---- row inverse norms (16 lanes share a row) -----------------------------
    float* invn = (float*)(smem + SM_INVN);
    #pragma unroll
    for (int p = 0; p < 8; p++) {
        float s = ssq[p];
        s += __shfl_xor_sync(0xffffffffu, s, 1);
        s += __shfl_xor_sync(0xffffffffu, s, 2);
        s += __shfl_xor_sync(0xffffffffu, s, 4);
        s += __shfl_xor_sync(0xffffffffu, s, 8);
        if (lc == 0) invn[rloc[p]] = 1.0f / fmaxf(sqrtf(s), 1e-12f);
    }
    __syncthreads();   // invn ready AND all warps past final mma (buffer reuse safe)

    // ---- epilogue 1: regs -> smem transpose buffer [q][TB_PAD] bf16 -----------
    {
        __nv_bfloat16* tb = (__nv_bfloat16*)(smem + SM_B0);
        const int q0 = qbase + (lane >> 2);
        #pragma unroll
        for (int nt = 0; nt < 8; nt++) {
            const int r0 = nbase + nt * 8 + (lane & 3) * 2;
            const float i0 = invn[r0], i1 = invn[r0 + 1];
            __nv_bfloat162 v01 = __floats2bfloat162_rn(acc[nt][0] * i0, acc[nt][1] * i1);
            __nv_bfloat162 v23 = __floats2bfloat162_rn(acc[nt][2] * i0, acc[nt][3] * i1);
            *(__nv_bfloat162*)&tb[ q0      * TB_PAD + r0] = v01;
            *(__nv_bfloat162*)&tb[(q0 + 8) * TB_PAD + r0] = v23;
        }
    }
    __syncthreads();

    // ---- epilogue 2: fused per-(q,tile) top-4 extraction ----------------------
    {
        const __nv_bfloat16* tb = (const __nv_bfloat16*)(smem + SM_B0);
        float* cv = (float*)(smem + SM_CV);
        int*   ci = (int*)(smem + SM_CI);
        const int q = tid >> 2, seg = tid & 3;

        float v4[TPT]; int i4[TPT];
        #pragma unroll
        for (int j = 0; j < TPT; j++) { v4[j] = -3.4e38f; i4[j] = 0x7fffffff; }
        #pragma unroll 8
        for (int r = 0; r < 32; r++) {
            float v = __bfloat162float(tb[q * TB_PAD + seg * 32 + r]);
            if (v > v4[TPT - 1]) {
                int j = TPT - 1;
                while (j > 0 && v > v4[j - 1]) { v4[j] = v4[j-1]; i4[j] = i4[j-1]; j--; }
                v4[j] = v; i4[j] = seg * 32 + r;
            }
        }
        #pragma unroll
        for (int j = 0; j < TPT; j++) { cv[tid * TPT + j] = v4[j]; ci[tid * TPT + j] = i4[j]; }
        __syncthreads();

        if (seg == 0) {
            float m4[TPT]; int mi[TPT];
            #pragma unroll
            for (int j = 0; j < TPT; j++) { m4[j] = -3.4e38f; mi[j] = 0x7fffffff; }
            for (int s = 0; s < 4; s++)
                #pragma unroll
                for (int j = 0; j < TPT; j++) {
                    float v = cv[(q * 4 + s) * TPT + j];
                    int  idx = ci[(q * 4 + s) * TPT + j];
                    if (v > m4[TPT - 1]) {
                        int t = TPT - 1;
                        while (t > 0 && v > m4[t - 1]) { m4[t] = m4[t-1]; mi[t] = mi[t-1]; t--; }
                        m4[t] = v; mi[t] = idx;
                    }
                }
            const long long tb0 = (long long)blockIdx.x * TILE_M;
            const size_t base = ((size_t)q * gridDim.x + blockIdx.x) * TPT;
            #pragma unroll
            for (int j = 0; j < TPT; j++) {
                g_ctv[base + j] = m4[j];
                g_cti[base + j] = (mi[j] == 0x7fffffff) ? 0x7fffffff : (int)(tb0 + mi[j]);
            }
        }
    }
}

// ---------------- kernel 3: merge candidates + exact fp32 rescore + output ---
__global__ __launch_bounds__(256, 1)
void merge_final_kernel(const float* __restrict__ bank, float* __restrict__ out,
                        int nrows, int k, int ntiles) {
    __shared__ float sv[256 * CAND];
    __shared__ int   si[256 * CAND];
    __shared__ float rv[CAND];
    __shared__ int   sid[CAND];
    const int q = blockIdx.x, tid = threadIdx.x;
    const int lane = tid & 31, warp = tid >> 5;

    // per-thread top-16 over this query's candidate stream (id-aware comparator)
    float v[CAND]; int id[CAND];
    #pragma unroll
    for (int i = 0; i < CAND; i++) { v[i] = -3.4e38f; id[i] = 0x7fffffff; }
    const size_t qbase = (size_t)q * ntiles * TPT;
    const int total = ntiles * TPT;
    for (int i = tid; i < total; i += 256) {
        float nv = g_ctv[qbase + i];
        int   ni = g_cti[qbase + i];
        if (ni >= nrows) continue;
        float lv = v[CAND - 1]; int li = id[CAND - 1];
        if (nv < lv || (nv == lv && ni >= li)) continue;
        int j = CAND - 1;
        while (j > 0 && (nv > v[j - 1] || (nv == v[j - 1] && ni < id[j - 1]))) {
            v[j] = v[j - 1]; id[j] = id[j - 1]; j--;
        }
        v[j] = nv; id[j] = ni;
    }
    #pragma unroll
    for (int i = 0; i < CAND; i++) { sv[tid * CAND + i] = v[i]; si[tid * CAND + i] = id[i]; }
    __syncthreads();

    // tree merge of sorted-16 lists (bounded reads, R8-proven pattern)
    for (int st = 128; st > 0; st >>= 1) {
        if (tid < st) {
            const int ao = tid * CAND, bo = (tid + st) * CAND;
            float ov[CAND]; int oi[CAND];
            int ia = 0, ib = 0;
            #pragma unroll
            for (int o = 0; o < CAND; o++) {
                float va = (ia < CAND) ? sv[ao + ia] : -3.4e38f;
                float vb = (ib < CAND) ? sv[bo + ib] : -3.4e38f;
                int   xa = si[ao + min(ia, CAND - 1)];
                int   xb = si[bo + min(ib, CAND - 1)];
                bool takeA;
                if (va > vb) takeA = true;
                else if (va < vb) takeA = false;
                else takeA = (xa <= xb);
                if (takeA) { ov[o] = va; oi[o] = xa; ia++; }
                else       { ov[o] = vb; oi[o] = xb; ib++; }
            }
            #pragma unroll
            for (int o = 0; o < CAND; o++) { sv[ao + o] = ov[o]; si[ao + o] = oi[o]; }
        }
        __syncthreads();
    }

    if (tid < CAND) sid[tid] = si[tid];
    __syncthreads();

    // exact fp32 rescore of the 16 survivors
    for (int c = warp; c < CAND; c += 8) {
        const int cid = sid[c];
        float val = -3.4e38f;
        if (cid >= 0 && cid < nrows) {
            const float4* b4 = (const float4*)(bank + (long long)cid * KDIM);
            const float4* q4 = (const float4*)(g_qn + q * KDIM);
            float dot = 0.f, ss = 0.f;
            #pragma unroll
            for (int i = 0; i < 6; i++) {
                float4 bb = b4[lane + i * 32];
                float4 qq = q4[lane + i * 32];
                dot = fmaf(qq.x, bb.x, fmaf(qq.y, bb.y, fmaf(qq.z, bb.z, fmaf(qq.w, bb.w, dot))));
                ss  = fmaf(bb.x, bb.x, fmaf(bb.y, bb.y, fmaf(bb.z, bb.z, fmaf(bb.w, bb.w, ss))));
            }
            #pragma unroll
            for (int o = 16; o; o >>= 1) {
                dot += __shfl_xor_sync(0xffffffffu, dot, o);
                ss  += __shfl_xor_sync(0xffffffffu, ss,  o);
            }
            val = dot / fmaxf(sqrtf(ss), 1e-12f);
        }
        if (lane == 0) rv[c] = val;
    }
    __syncthreads();

    if (tid == 0) {
        bool used[CAND];
        #pragma unroll
        for (int i = 0; i < CAND; i++) used[i] = false;
        for (int j = 0; j < k; j++) {
            int best = -1; float bvv = -3.4e38f;
            for (int i = 0; i < CAND; i++) {
                if (used[i]) continue;
                if (best < 0 || rv[i] > bvv ||
                    (rv[i] == bvv && sid[i] < sid[best])) { bvv = rv[i]; best = i; }
            }
            used[best] = true;
            out[q * k + j]          = bvv;
            out[NQ * k + q * k + j] = (float)sid[best];
        }
    }
}

// ---------------- launch -----------------------------------------------------
extern "C" void kernel_launch(void* const* d_in, const int* in_sizes, int n_in,
                              void* d_out, int out_size) {
    const float* query = (const float*)d_in[0];
    const float* bank  = (const float*)d_in[1];
    const int nrows = in_sizes[1] / KDIM;
    const int k = out_size / (2 * NQ);

    cudaFuncSetAttribute(score_kernel, cudaFuncAttributeMaxDynamicSharedMemorySize, SCORE_SMEM);

    norm_q_kernel<<<NQ, 256>>>(query);

    const int ntiles = (nrows + TILE_M - 1) / TILE_M;
    score_kernel<<<ntiles, 256, SCORE_SMEM>>>(bank, nrows);

    merge_final_kernel<<<NQ, 256>>>(bank, (float*)d_out, nrows, k, ntiles);
}

// round 15
// speedup vs baseline: 3.0176x; 1.0114x over previous
#include <cuda_runtime.h>
#include <cuda_fp16.h>
#include <cuda_bf16.h>
#include <math.h>

// ---------------- problem constants ------------------------------------------
#define NQ      64
#define KDIM    768
#define TILE_M  128                 // bank rows per CTA tile
#define CHUNK_K 64                  // K elems per chunk (fp16 row = 128 B)
#define NCHUNK  (KDIM / CHUNK_K)    // 12
#define MAXROWS 500000
#define MAXTILES ((MAXROWS + TILE_M - 1) / TILE_M)   // 3907
#define TPT     4                   // candidates kept per (q, tile)
#define CAND    16                  // candidates exactly rescored per query
#define TB_PAD  136                 // transpose buffer row pitch (bf16 elems)

// ---------------- smem layout (score kernel) ---------------------------------
#define SM_INVN 0                                   // float[128]
#define SM_Q    1024                                // 12 chunks x 64 q x 128 B = 98304
#define SM_B0   (SM_Q + NCHUNK * 64 * 128)          // 99328: B buf 0 (16 KB)
#define SM_B1   (SM_B0 + TILE_M * 128)              // 115712: B buf 1 (16 KB)
#define SM_CV   (SM_B1 + 2048)                      // float[256*4] (tb ends at SM_B1+1024)
#define SM_CI   (SM_CV + 4096)                      // int[256*4]
#define SCORE_SMEM (SM_B1 + TILE_M * 128)           // 132096

// ---------------- device scratch (allocation-free rule) ----------------------
__device__ __align__(16) float  g_qn [NQ * KDIM];                     // fp32 normalized queries
__device__ __align__(16) __half g_qnh[NQ * KDIM];                     // fp16 copy
__device__ __align__(16) float g_ctv[(size_t)NQ * MAXTILES * TPT];    // per-tile cand vals
__device__ __align__(16) int   g_cti[(size_t)NQ * MAXTILES * TPT];    // per-tile cand ids

// ---------------- kernel 1: normalize queries --------------------------------
__global__ void norm_q_kernel(const float* __restrict__ q) {
    __shared__ float red[256];
    int qi = blockIdx.x, tid = threadIdx.x;
    const float* qr = q + qi * KDIM;
    float v0 = qr[tid], v1 = qr[tid + 256], v2 = qr[tid + 512];
    red[tid] = v0 * v0 + v1 * v1 + v2 * v2;
    __syncthreads();
    for (int st = 128; st > 0; st >>= 1) {
        if (tid < st) red[tid] += red[tid + st];
        __syncthreads();
    }
    float inv = 1.0f / fmaxf(sqrtf(red[0]), 1e-12f);
    float o0 = v0 * inv, o1 = v1 * inv, o2 = v2 * inv;
    g_qn[qi * KDIM + tid      ] = o0;
    g_qn[qi * KDIM + tid + 256] = o1;
    g_qn[qi * KDIM + tid + 512] = o2;
    g_qnh[qi * KDIM + tid      ] = __float2half(o0);
    g_qnh[qi * KDIM + tid + 256] = __float2half(o1);
    g_qnh[qi * KDIM + tid + 512] = __float2half(o2);
}

// ---------------- kernel 2: f16-accum mma score + fused per-tile top-4 -------
__device__ __forceinline__ void ld_chunk(float4 (&f)[8], const float* const (&rp)[8],
                                         const bool (&vld)[8], int c) {
    #pragma unroll
    for (int p = 0; p < 8; p++) {
        if (vld[p]) f[p] = *(const float4*)(rp[p] + c * CHUNK_K);
        else        f[p] = make_float4(0.f, 0.f, 0.f, 0.f);
    }
}

__device__ __forceinline__ void ldsm_x4(unsigned& r0, unsigned& r1, unsigned& r2,
                                        unsigned& r3, unsigned addr) {
    asm volatile("ldmatrix.sync.aligned.m8n8.x4.shared.b16 {%0,%1,%2,%3}, [%4];"
                 : "=r"(r0), "=r"(r1), "=r"(r2), "=r"(r3) : "r"(addr));
}

__device__ __forceinline__ unsigned s2u(const void* p) {
    unsigned a;
    asm("{ .reg .u64 t; cvta.to.shared.u64 t, %1; cvt.u32.u64 %0, t; }" : "=r"(a) : "l"(p));
    return a;
}

__global__ __launch_bounds__(256, 1)
void score_kernel(const float* __restrict__ bank, int nrows) {
    extern __shared__ char smem[];
    const unsigned sbase = s2u(smem);
    const int tid = threadIdx.x, warp = tid >> 5, lane = tid & 31;
    const int lr = lane >> 4, lc = lane & 15;

    // ---- global load mapping: 16 lanes per row, line-contiguous LDG.128 ------
    int rloc[8]; const float* rp[8]; bool vld[8]; float ssq[8];
    #pragma unroll
    for (int p = 0; p < 8; p++) {
        int r = p * 16 + warp * 2 + lr;
        rloc[p] = r;
        long long grow = (long long)blockIdx.x * TILE_M + r;
        vld[p] = grow < (long long)nrows;
        rp[p]  = bank + grow * (long long)KDIM + lc * 4;
        ssq[p] = 0.f;
    }
    const int scol = (lc * 8) ^ (((warp * 2 + lr) & 7) << 4);  // row&7 is p-invariant

    // ---- stage all queries (fp16): [chunk][64 q][128 B], XOR-swizzled --------
    for (int i = tid; i < NQ * KDIM / 4; i += 256) {
        int qi  = i / 192;
        int rem = i - qi * 192;
        int c   = rem >> 4;
        int k4  = rem & 15;
        uint2 v = ((const uint2*)g_qnh)[i];
        *(uint2*)(smem + SM_Q + c * 8192 + qi * 128 + ((k4 * 8) ^ ((qi & 7) << 4))) = v;
    }

    // ---- mma thread constants (R8/R14-proven layout) --------------------------
    const int qbase = (warp & 3) * 16;          // m (query) strip
    const int nbase = (warp >> 2) * 64;         // n (bank row) strip
    const int arow  = qbase + ((lane >> 3) & 1) * 8 + (lane & 7);
    const int axtr  = (lane >> 4) * 16;
    const int brow0 = nbase + ((lane >> 4) & 1) * 8 + (lane & 7);   // + pair*16
    const int bxtr  = ((lane >> 3) & 1) * 16;
    const int lsw   = (lane & 7) << 4;

    unsigned hacc[8][2];                // f16x2 accumulators (zeroed per chunk)
    float    facc[8][4];                // fp32 folded accumulators
    #pragma unroll
    for (int i = 0; i < 8; i++) {
        hacc[i][0] = 0u; hacc[i][1] = 0u;
        #pragma unroll
        for (int j = 0; j < 4; j++) facc[i][j] = 0.f;
    }

    float4 f[8];
    ld_chunk(f, rp, vld, 0);           // prologue: chunk 0 in flight

    for (int c = 0; c < NCHUNK; c++) {
        const unsigned bb = sbase + ((c & 1) ? SM_B1 : SM_B0);
        // convert + STS chunk c into buffer c&1 (waits on its LDGs via scoreboard)
        #pragma unroll
        for (int p = 0; p < 8; p++) {
            float4 fv = f[p];
            ssq[p] += fv.x * fv.x + fv.y * fv.y + fv.z * fv.z + fv.w * fv.w;
            __half2 p0 = __floats2half2_rn(fv.x, fv.y);
            __half2 p1 = __floats2half2_rn(fv.z, fv.w);
            uint2 u;
            u.x = *(unsigned*)&p0;
            u.y = *(unsigned*)&p1;
            *(uint2*)(smem + ((c & 1) ? SM_B1 : SM_B0) + rloc[p] * 128 + scol) = u;
        }
        __syncthreads();   // single sync: STS(c) visible; double-buffer makes the
                           // fast-warp STS(c+1) (other buffer) safe vs mma(c).

        // next chunk's loads issued before mma work (latency hidden behind mma)
        if (c + 1 < NCHUNK) ld_chunk(f, rp, vld, c + 1);

        // f16-accum mma over chunk c: 4 k16 steps x 8 ntiles
        const unsigned qb = sbase + SM_Q + c * 8192;
        #pragma unroll
        for (int kk = 0; kk < 4; kk++) {
            unsigned a0, a1, a2, a3;
            ldsm_x4(a0, a1, a2, a3,
                    qb + arow * 128 + ((kk * 32 + axtr) ^ lsw));
            #pragma unroll
            for (int pair = 0; pair < 4; pair++) {
                unsigned b0, b1, b2, b3;
                ldsm_x4(b0, b1, b2, b3,
                        bb + (brow0 + pair * 16) * 128 + ((kk * 32 + bxtr) ^ lsw));
                asm volatile(
                    "mma.sync.aligned.m16n8k16.row.col.f16.f16.f16.f16 "
                    "{%0,%1}, {%2,%3,%4,%5}, {%6,%7}, {%0,%1};\n"
                    : "+r"(hacc[pair*2][0]), "+r"(hacc[pair*2][1])
                    : "r"(a0), "r"(a1), "r"(a2), "r"(a3), "r"(b0), "r"(b1));
                asm volatile(
                    "mma.sync.aligned.m16n8k16.row.col.f16.f16.f16.f16 "
                    "{%0,%1}, {%2,%3,%4,%5}, {%6,%7}, {%0,%1};\n"
                    : "+r"(hacc[pair*2+1][0]), "+r"(hacc[pair*2+1][1])
                    : "r"(a0), "r"(a1), "r"(a2), "r"(a3), "r"(b2), "r"(b3));
            }
        }

        // fold f16 partial sums into fp32 (bounds accumulation error per chunk)
        #pragma unroll
        for (int nt = 0; nt < 8; nt++) {
            float2 f0 = __half22float2(*(__half2*)&hacc[nt][0]);
            float2 f1 = __half22float2(*(__half2*)&hacc[nt][1]);
            facc[nt][0] += f0.x; facc[nt][1] += f0.y;
            facc[nt][2] += f1.x; facc[nt][3] += f1.y;
            hacc[nt][0] = 0u; hacc[nt][1] = 0u;
        }
    }

    // ---- row inverse norms (16 lanes share a row) -----------------------------
    float* invn = (float*)(smem + SM_INVN);
    #pragma unroll
    for (int p = 0; p < 8; p++) {
        float s = ssq[p];
        s += __shfl_xor_sync(0xffffffffu, s, 1);
        s += __shfl_xor_sync(0xffffffffu, s, 2);
        s += __shfl_xor_sync(0xffffffffu, s, 4);
        s += __shfl_xor_sync(0xffffffffu, s, 8);
        if (lc == 0) invn[rloc[p]] = 1.0f / fmaxf(sqrtf(s), 1e-12f);
    }
    __syncthreads();   // invn ready AND all warps past final mma (buffer reuse safe)

    // ---- epilogue 1: regs -> smem transpose buffer [q][TB_PAD] bf16 -----------
    {
        __nv_bfloat16* tb = (__nv_bfloat16*)(smem + SM_B0);
        const int q0 = qbase + (lane >> 2);
        #pragma unroll
        for (int nt = 0; nt < 8; nt++) {
            const int r0 = nbase + nt * 8 + (lane & 3) * 2;
            const float i0 = invn[r0], i1 = invn[r0 + 1];
            __nv_bfloat162 v01 = __floats2bfloat162_rn(facc[nt][0] * i0, facc[nt][1] * i1);
            __nv_bfloat162 v23 = __floats2bfloat162_rn(facc[nt][2] * i0, facc[nt][3] * i1);
            *(__nv_bfloat162*)&tb[ q0      * TB_PAD + r0] = v01;
            *(__nv_bfloat162*)&tb[(q0 + 8) * TB_PAD + r0] = v23;
        }
    }
    __syncthreads();

    // ---- epilogue 2: fused per-(q,tile) top-4 extraction ----------------------
    {
        const __nv_bfloat16* tb = (const __nv_bfloat16*)(smem + SM_B0);
        float* cv = (float*)(smem + SM_CV);
        int*   ci = (int*)(smem + SM_CI);
        const int q = tid >> 2, seg = tid & 3;

        float v4[TPT]; int i4[TPT];
        #pragma unroll
        for (int j = 0; j < TPT; j++) { v4[j] = -3.4e38f; i4[j] = 0x7fffffff; }
        #pragma unroll 8
        for (int r = 0; r < 32; r++) {
            float v = __bfloat162float(tb[q * TB_PAD + seg * 32 + r]);
            if (v > v4[TPT - 1]) {
                int j = TPT - 1;
                while (j > 0 && v > v4[j - 1]) { v4[j] = v4[j-1]; i4[j] = i4[j-1]; j--; }
                v4[j] = v; i4[j] = seg * 32 + r;
            }
        }
        #pragma unroll
        for (int j = 0; j < TPT; j++) { cv[tid * TPT + j] = v4[j]; ci[tid * TPT + j] = i4[j]; }
        __syncthreads();

        if (seg == 0) {
            float m4[TPT]; int mi[TPT];
            #pragma unroll
            for (int j = 0; j < TPT; j++) { m4[j] = -3.4e38f; mi[j] = 0x7fffffff; }
            for (int s = 0; s < 4; s++)
                #pragma unroll
                for (int j = 0; j < TPT; j++) {
                    float v = cv[(q * 4 + s) * TPT + j];
                    int  idx = ci[(q * 4 + s) * TPT + j];
                    if (v > m4[TPT - 1]) {
                        int t = TPT - 1;
                        while (t > 0 && v > m4[t - 1]) { m4[t] = m4[t-1]; mi[t] = mi[t-1]; t--; }
                        m4[t] = v; mi[t] = idx;
                    }
                }
            const long long tb0 = (long long)blockIdx.x * TILE_M;
            const size_t base = ((size_t)q * gridDim.x + blockIdx.x) * TPT;
            #pragma unroll
            for (int j = 0; j < TPT; j++) {
                g_ctv[base + j] = m4[j];
                g_cti[base + j] = (mi[j] == 0x7fffffff) ? 0x7fffffff : (int)(tb0 + mi[j]);
            }
        }
    }
}

// ---------------- kernel 3: merge candidates + exact fp32 rescore + output ---
__global__ __launch_bounds__(256, 1)
void merge_final_kernel(const float* __restrict__ bank, float* __restrict__ out,
                        int nrows, int k, int ntiles) {
    __shared__ float sv[256 * CAND];
    __shared__ int   si[256 * CAND];
    __shared__ float rv[CAND];
    __shared__ int   sid[CAND];
    const int q = blockIdx.x, tid = threadIdx.x;
    const int lane = tid & 31, warp = tid >> 5;

    // per-thread top-16 over this query's candidate stream (id-aware comparator)
    float v[CAND]; int id[CAND];
    #pragma unroll
    for (int i = 0; i < CAND; i++) { v[i] = -3.4e38f; id[i] = 0x7fffffff; }
    const size_t qbase = (size_t)q * ntiles * TPT;
    const int total = ntiles * TPT;
    for (int i = tid; i < total; i += 256) {
        float nv = g_ctv[qbase + i];
        int   ni = g_cti[qbase + i];
        if (ni >= nrows) continue;
        float lv = v[CAND - 1]; int li = id[CAND - 1];
        if (nv < lv || (nv == lv && ni >= li)) continue;
        int j = CAND - 1;
        while (j > 0 && (nv > v[j - 1] || (nv == v[j - 1] && ni < id[j - 1]))) {
            v[j] = v[j - 1]; id[j] = id[j - 1]; j--;
        }
        v[j] = nv; id[j] = ni;
    }
    #pragma unroll
    for (int i = 0; i < CAND; i++) { sv[tid * CAND + i] = v[i]; si[tid * CAND + i] = id[i]; }
    __syncthreads();

    // tree merge of sorted-16 lists (bounded reads)
    for (int st = 128; st > 0; st >>= 1) {
        if (tid < st) {
            const int ao = tid * CAND, bo = (tid + st) * CAND;
            float ov[CAND]; int oi[CAND];
            int ia = 0, ib = 0;
            #pragma unroll
            for (int o = 0; o < CAND; o++) {
                float va = (ia < CAND) ? sv[ao + ia] : -3.4e38f;
                float vb = (ib < CAND) ? sv[bo + ib] : -3.4e38f;
                int   xa = si[ao + min(ia, CAND - 1)];
                int   xb = si[bo + min(ib, CAND - 1)];
                bool takeA;
                if (va > vb) takeA = true;
                else if (va < vb) takeA = false;
                else takeA = (xa <= xb);
                if (takeA) { ov[o] = va; oi[o] = xa; ia++; }
                else       { ov[o] = vb; oi[o] = xb; ib++; }
            }
            #pragma unroll
            for (int o = 0; o < CAND; o++) { sv[ao + o] = ov[o]; si[ao + o] = oi[o]; }
        }
        __syncthreads();
    }

    if (tid < CAND) sid[tid] = si[tid];
    __syncthreads();

    // exact fp32 rescore of the 16 survivors
    for (int c = warp; c < CAND; c += 8) {
        const int cid = sid[c];
        float val = -3.4e38f;
        if (cid >= 0 && cid < nrows) {
            const float4* b4 = (const float4*)(bank + (long long)cid * KDIM);
            const float4* q4 = (const float4*)(g_qn + q * KDIM);
            float dot = 0.f, ss = 0.f;
            #pragma unroll
            for (int i = 0; i < 6; i++) {
                float4 bb = b4[lane + i * 32];
                float4 qq = q4[lane + i * 32];
                dot = fmaf(qq.x, bb.x, fmaf(qq.y, bb.y, fmaf(qq.z, bb.z, fmaf(qq.w, bb.w, dot))));
                ss  = fmaf(bb.x, bb.x, fmaf(bb.y, bb.y, fmaf(bb.z, bb.z, fmaf(bb.w, bb.w, ss))));
            }
            #pragma unroll
            for (int o = 16; o; o >>= 1) {
                dot += __shfl_xor_sync(0xffffffffu, dot, o);
                ss  += __shfl_xor_sync(0xffffffffu, ss,  o);
            }
            val = dot / fmaxf(sqrtf(ss), 1e-12f);
        }
        if (lane == 0) rv[c] = val;
    }
    __syncthreads();

    if (tid == 0) {
        bool used[CAND];
        #pragma unroll
        for (int i = 0; i < CAND; i++) used[i] = false;
        for (int j = 0; j < k; j++) {
            int best = -1; float bvv = -3.4e38f;
            for (int i = 0; i < CAND; i++) {
                if (used[i]) continue;
                if (best < 0 || rv[i] > bvv ||
                    (rv[i] == bvv && sid[i] < sid[best])) { bvv = rv[i]; best = i; }
            }
            used[best] = true;
            out[q * k + j]          = bvv;
            out[NQ * k + q * k + j] = (float)sid[best];
        }
    }
}

// ---------------- launch -----------------------------------------------------
extern "C" void kernel_launch(void* const* d_in, const int* in_sizes, int n_in,
                              void* d_out, int out_size) {
    const float* query = (const float*)d_in[0];
    const float* bank  = (const float*)d_in[1];
    const int nrows = in_sizes[1] / KDIM;
    const int k = out_size / (2 * NQ);

    cudaFuncSetAttribute(score_kernel, cudaFuncAttributeMaxDynamicSharedMemorySize, SCORE_SMEM);

    norm_q_kernel<<<NQ, 256>>>(query);

    const int ntiles = (nrows + TILE_M - 1) / TILE_M;
    score_kernel<<<ntiles, 256, SCORE_SMEM>>>(bank, nrows);

    merge_final_kernel<<<NQ, 256>>>(bank, (float*)d_out, nrows, k, ntiles);
}

// round 16
// speedup vs baseline: 4.2679x; 1.4143x over previous
#include <cuda_runtime.h>
#include <cuda_fp16.h>
#include <cuda_bf16.h>
#include <math.h>

// ---------------- problem constants ------------------------------------------
#define NQ      64
#define KDIM    768
#define TILE_M  128                 // bank rows per CTA tile
#define CHUNK_K 64                  // K elems per chunk (fp16 row = 128 B)
#define NCHUNK  (KDIM / CHUNK_K)    // 12
#define MAXROWS 500000
#define MAXTILES ((MAXROWS + TILE_M - 1) / TILE_M)   // 3907
#define TPT     4                   // candidates kept per (q, tile)
#define CAND    16                  // candidates exactly rescored per query
#define TB_PAD  136                 // transpose buffer row pitch (bf16 elems)

// ---------------- smem layout (score kernel): 50 KB -> 2 CTAs/SM -------------
#define SM_INVN 0                                   // float[128]
#define SM_BUF0 1024                                // Q 8KB + B 16KB
#define SM_BUF1 (SM_BUF0 + 24576)                   // 25600
#define SM_TB   1024                                // epilogue transpose (overlay buf0)
#define SM_CV   SM_BUF1                             // float[256*4] (overlay buf1)
#define SM_CI   (SM_BUF1 + 4096)                    // int[256*4]
#define SCORE_SMEM (SM_BUF1 + 24576)                // 50176

// ---------------- device scratch (allocation-free rule) ----------------------
__device__ __align__(16) float  g_qn [NQ * KDIM];                     // fp32 normalized queries
__device__ __align__(16) char   g_qstage[NCHUNK * 8192];              // swizzled per-chunk Q (fp16)
__device__ __align__(16) float g_ctv[(size_t)NQ * MAXTILES * TPT];    // per-tile cand vals
__device__ __align__(16) int   g_cti[(size_t)NQ * MAXTILES * TPT];    // per-tile cand ids

// ---------------- kernel 1: normalize queries + staged-layout fp16 copy ------
__global__ void norm_q_kernel(const float* __restrict__ q) {
    __shared__ float red[256];
    int qi = blockIdx.x, tid = threadIdx.x;
    const float* qr = q + qi * KDIM;
    float v0 = qr[tid], v1 = qr[tid + 256], v2 = qr[tid + 512];
    red[tid] = v0 * v0 + v1 * v1 + v2 * v2;
    __syncthreads();
    for (int st = 128; st > 0; st >>= 1) {
        if (tid < st) red[tid] += red[tid + st];
        __syncthreads();
    }
    float inv = 1.0f / fmaxf(sqrtf(red[0]), 1e-12f);
    float o[3] = {v0 * inv, v1 * inv, v2 * inv};
    g_qn[qi * KDIM + tid      ] = o[0];
    g_qn[qi * KDIM + tid + 256] = o[1];
    g_qn[qi * KDIM + tid + 512] = o[2];
    // write fp16 into the exact swizzled per-chunk staging layout
    #pragma unroll
    for (int j = 0; j < 3; j++) {
        const int k = tid + j * 256;
        const int c = k >> 6, kr = k & 63;
        const int off = c * 8192 + qi * 128 + (((kr >> 2) * 8) ^ ((qi & 7) << 4)) + (kr & 3) * 2;
        *(__half*)(g_qstage + off) = __float2half(o[j]);
    }
}

// ---------------- kernel 2: mma score (2 CTAs/SM) + fused per-tile top-4 -----
__device__ __forceinline__ void ld_bank(float4 (&f)[8], const float* const (&rp)[8],
                                        const bool (&vld)[8], int c) {
    #pragma unroll
    for (int p = 0; p < 8; p++) {
        if (vld[p]) f[p] = *(const float4*)(rp[p] + c * CHUNK_K);
        else        f[p] = make_float4(0.f, 0.f, 0.f, 0.f);
    }
}
__device__ __forceinline__ void ld_q(uint4 (&qf)[2], int c, int tid) {
    const uint4* src = (const uint4*)(g_qstage) + c * 512;
    qf[0] = src[tid * 2];
    qf[1] = src[tid * 2 + 1];
}

__device__ __forceinline__ void ldsm_x4(unsigned& r0, unsigned& r1, unsigned& r2,
                                        unsigned& r3, unsigned addr) {
    asm volatile("ldmatrix.sync.aligned.m8n8.x4.shared.b16 {%0,%1,%2,%3}, [%4];"
                 : "=r"(r0), "=r"(r1), "=r"(r2), "=r"(r3) : "r"(addr));
}

__device__ __forceinline__ unsigned s2u(const void* p) {
    unsigned a;
    asm("{ .reg .u64 t; cvta.to.shared.u64 t, %1; cvt.u32.u64 %0, t; }" : "=r"(a) : "l"(p));
    return a;
}

__global__ __launch_bounds__(256, 2)
void score_kernel(const float* __restrict__ bank, int nrows) {
    extern __shared__ char smem[];
    const unsigned sbase = s2u(smem);
    const int tid = threadIdx.x, warp = tid >> 5, lane = tid & 31;
    const int lr = lane >> 4, lc = lane & 15;

    // ---- global load mapping: 16 lanes per row, line-contiguous LDG.128 ------
    int rloc[8]; const float* rp[8]; bool vld[8]; float ssq[8];
    #pragma unroll
    for (int p = 0; p < 8; p++) {
        int r = p * 16 + warp * 2 + lr;
        rloc[p] = r;
        long long grow = (long long)blockIdx.x * TILE_M + r;
        vld[p] = grow < (long long)nrows;
        rp[p]  = bank + grow * (long long)KDIM + lc * 4;
        ssq[p] = 0.f;
    }
    const int scol = (lc * 8) ^ (((warp * 2 + lr) & 7) << 4);  // row&7 is p-invariant

    // ---- mma thread constants (R14-proven layout) -----------------------------
    const int qbase = (warp & 3) * 16;          // m (query) strip
    const int nbase = (warp >> 2) * 64;         // n (bank row) strip
    const int arow  = qbase + ((lane >> 3) & 1) * 8 + (lane & 7);
    const int axtr  = (lane >> 4) * 16;
    const int brow0 = nbase + ((lane >> 4) & 1) * 8 + (lane & 7);   // + pair*16
    const int bxtr  = ((lane >> 3) & 1) * 16;
    const int lsw   = (lane & 7) << 4;

    float acc[8][4];
    #pragma unroll
    for (int i = 0; i < 8; i++)
        #pragma unroll
        for (int j = 0; j < 4; j++) acc[i][j] = 0.f;

    float4 f[8];
    uint4  qf[2];
    ld_bank(f, rp, vld, 0);
    ld_q(qf, 0, tid);

    for (int c = 0; c < NCHUNK; c++) {
        const unsigned buf = sbase + ((c & 1) ? SM_BUF1 : SM_BUF0);
        char* bufp = smem + ((c & 1) ? SM_BUF1 : SM_BUF0);
        // stage Q chunk (straight copy of pre-swizzled slice)
        ((uint4*)bufp)[tid * 2    ] = qf[0];
        ((uint4*)bufp)[tid * 2 + 1] = qf[1];
        // stage B chunk: convert + STS (waits on its LDGs via scoreboard)
        #pragma unroll
        for (int p = 0; p < 8; p++) {
            float4 fv = f[p];
            ssq[p] += fv.x * fv.x + fv.y * fv.y + fv.z * fv.z + fv.w * fv.w;
            __half2 p0 = __floats2half2_rn(fv.x, fv.y);
            __half2 p1 = __floats2half2_rn(fv.z, fv.w);
            uint2 u;
            u.x = *(unsigned*)&p0;
            u.y = *(unsigned*)&p1;
            *(uint2*)(bufp + 8192 + rloc[p] * 128 + scol) = u;
        }
        __syncthreads();   // single sync: stage(c) visible; double-buffer makes the
                           // fast-warp stage(c+1) (other buffer) safe vs mma(c).

        // next chunk's loads issued before mma work (latency hidden behind mma)
        if (c + 1 < NCHUNK) { ld_bank(f, rp, vld, c + 1); ld_q(qf, c + 1, tid); }

        // mma over chunk c: 4 k16 steps x 8 ntiles
        const unsigned qb = buf;
        const unsigned bb = buf + 8192;
        #pragma unroll
        for (int kk = 0; kk < 4; kk++) {
            unsigned a0, a1, a2, a3;
            ldsm_x4(a0, a1, a2, a3,
                    qb + arow * 128 + ((kk * 32 + axtr) ^ lsw));
            #pragma unroll
            for (int pair = 0; pair < 4; pair++) {
                unsigned b0, b1, b2, b3;
                ldsm_x4(b0, b1, b2, b3,
                        bb + (brow0 + pair * 16) * 128 + ((kk * 32 + bxtr) ^ lsw));
                asm volatile(
                    "mma.sync.aligned.m16n8k16.row.col.f32.f16.f16.f32 "
                    "{%0,%1,%2,%3}, {%4,%5,%6,%7}, {%8,%9}, {%0,%1,%2,%3};\n"
                    : "+f"(acc[pair*2][0]), "+f"(acc[pair*2][1]),
                      "+f"(acc[pair*2][2]), "+f"(acc[pair*2][3])
                    : "r"(a0), "r"(a1), "r"(a2), "r"(a3), "r"(b0), "r"(b1));
                asm volatile(
                    "mma.sync.aligned.m16n8k16.row.col.f32.f16.f16.f32 "
                    "{%0,%1,%2,%3}, {%4,%5,%6,%7}, {%8,%9}, {%0,%1,%2,%3};\n"
                    : "+f"(acc[pair*2+1][0]), "+f"(acc[pair*2+1][1]),
                      "+f"(acc[pair*2+1][2]), "+f"(acc[pair*2+1][3])
                    : "r"(a0), "r"(a1), "r"(a2), "r"(a3), "r"(b2), "r"(b3));
            }
        }
    }

    // ---- row inverse norms (16 lanes share a row) -----------------------------
    float* invn = (float*)(smem + SM_INVN);
    #pragma unroll
    for (int p = 0; p < 8; p++) {
        float s = ssq[p];
        s += __shfl_xor_sync(0xffffffffu, s, 1);
        s += __shfl_xor_sync(0xffffffffu, s, 2);
        s += __shfl_xor_sync(0xffffffffu, s, 4);
        s += __shfl_xor_sync(0xffffffffu, s, 8);
        if (lc == 0) invn[rloc[p]] = 1.0f / fmaxf(sqrtf(s), 1e-12f);
    }
    __syncthreads();   // invn ready AND all warps past final mma (buffer reuse safe)

    // ---- epilogue 1: regs -> smem transpose buffer [q][TB_PAD] bf16 -----------
    {
        __nv_bfloat16* tb = (__nv_bfloat16*)(smem + SM_TB);
        const int q0 = qbase + (lane >> 2);
        #pragma unroll
        for (int nt = 0; nt < 8; nt++) {
            const int r0 = nbase + nt * 8 + (lane & 3) * 2;
            const float i0 = invn[r0], i1 = invn[r0 + 1];
            __nv_bfloat162 v01 = __floats2bfloat162_rn(acc[nt][0] * i0, acc[nt][1] * i1);
            __nv_bfloat162 v23 = __floats2bfloat162_rn(acc[nt][2] * i0, acc[nt][3] * i1);
            *(__nv_bfloat162*)&tb[ q0      * TB_PAD + r0] = v01;
            *(__nv_bfloat162*)&tb[(q0 + 8) * TB_PAD + r0] = v23;
        }
    }
    __syncthreads();

    // ---- epilogue 2: fused per-(q,tile) top-4 extraction ----------------------
    {
        const __nv_bfloat16* tb = (const __nv_bfloat16*)(smem + SM_TB);
        float* cv = (float*)(smem + SM_CV);
        int*   ci = (int*)(smem + SM_CI);
        const int q = tid >> 2, seg = tid & 3;

        float v4[TPT]; int i4[TPT];
        #pragma unroll
        for (int j = 0; j < TPT; j++) { v4[j] = -3.4e38f; i4[j] = 0x7fffffff; }
        #pragma unroll 8
        for (int r = 0; r < 32; r++) {
            float v = __bfloat162float(tb[q * TB_PAD + seg * 32 + r]);
            if (v > v4[TPT - 1]) {
                int j = TPT - 1;
                while (j > 0 && v > v4[j - 1]) { v4[j] = v4[j-1]; i4[j] = i4[j-1]; j--; }
                v4[j] = v; i4[j] = seg * 32 + r;
            }
        }
        #pragma unroll
        for (int j = 0; j < TPT; j++) { cv[tid * TPT + j] = v4[j]; ci[tid * TPT + j] = i4[j]; }
        __syncthreads();

        if (seg == 0) {
            float m4[TPT]; int mi[TPT];
            #pragma unroll
            for (int j = 0; j < TPT; j++) { m4[j] = -3.4e38f; mi[j] = 0x7fffffff; }
            for (int s = 0; s < 4; s++)
                #pragma unroll
                for (int j = 0; j < TPT; j++) {
                    float v = cv[(q * 4 + s) * TPT + j];
                    int  idx = ci[(q * 4 + s) * TPT + j];
                    if (v > m4[TPT - 1]) {
                        int t = TPT - 1;
                        while (t > 0 && v > m4[t - 1]) { m4[t] = m4[t-1]; mi[t] = mi[t-1]; t--; }
                        m4[t] = v; mi[t] = idx;
                    }
                }
            const long long tb0 = (long long)blockIdx.x * TILE_M;
            const size_t base = ((size_t)q * gridDim.x + blockIdx.x) * TPT;
            #pragma unroll
            for (int j = 0; j < TPT; j++) {
                g_ctv[base + j] = m4[j];
                g_cti[base + j] = (mi[j] == 0x7fffffff) ? 0x7fffffff : (int)(tb0 + mi[j]);
            }
        }
    }
}

// ---------------- kernel 3: merge candidates + exact fp32 rescore + output ---
__global__ __launch_bounds__(256, 1)
void merge_final_kernel(const float* __restrict__ bank, float* __restrict__ out,
                        int nrows, int k, int ntiles) {
    __shared__ float sv[256 * CAND];
    __shared__ int   si[256 * CAND];
    __shared__ float rv[CAND];
    __shared__ int   sid[CAND];
    const int q = blockIdx.x, tid = threadIdx.x;
    const int lane = tid & 31, warp = tid >> 5;

    // per-thread top-16 over this query's candidate stream (id-aware comparator)
    float v[CAND]; int id[CAND];
    #pragma unroll
    for (int i = 0; i < CAND; i++) { v[i] = -3.4e38f; id[i] = 0x7fffffff; }
    const size_t qbase = (size_t)q * ntiles * TPT;
    const int total = ntiles * TPT;
    for (int i = tid; i < total; i += 256) {
        float nv = g_ctv[qbase + i];
        int   ni = g_cti[qbase + i];
        if (ni >= nrows) continue;
        float lv = v[CAND - 1]; int li = id[CAND - 1];
        if (nv < lv || (nv == lv && ni >= li)) continue;
        int j = CAND - 1;
        while (j > 0 && (nv > v[j - 1] || (nv == v[j - 1] && ni < id[j - 1]))) {
            v[j] = v[j - 1]; id[j] = id[j - 1]; j--;
        }
        v[j] = nv; id[j] = ni;
    }
    #pragma unroll
    for (int i = 0; i < CAND; i++) { sv[tid * CAND + i] = v[i]; si[tid * CAND + i] = id[i]; }
    __syncthreads();

    // tree merge of sorted-16 lists (bounded reads)
    for (int st = 128; st > 0; st >>= 1) {
        if (tid < st) {
            const int ao = tid * CAND, bo = (tid + st) * CAND;
            float ov[CAND]; int oi[CAND];
            int ia = 0, ib = 0;
            #pragma unroll
            for (int o = 0; o < CAND; o++) {
                float va = (ia < CAND) ? sv[ao + ia] : -3.4e38f;
                float vb = (ib < CAND) ? sv[bo + ib] : -3.4e38f;
                int   xa = si[ao + min(ia, CAND - 1)];
                int   xb = si[bo + min(ib, CAND - 1)];
                bool takeA;
                if (va > vb) takeA = true;
                else if (va < vb) takeA = false;
                else takeA = (xa <= xb);
                if (takeA) { ov[o] = va; oi[o] = xa; ia++; }
                else       { ov[o] = vb; oi[o] = xb; ib++; }
            }
            #pragma unroll
            for (int o = 0; o < CAND; o++) { sv[ao + o] = ov[o]; si[ao + o] = oi[o]; }
        }
        __syncthreads();
    }

    if (tid < CAND) sid[tid] = si[tid];
    __syncthreads();

    // exact fp32 rescore of the 16 survivors
    for (int c = warp; c < CAND; c += 8) {
        const int cid = sid[c];
        float val = -3.4e38f;
        if (cid >= 0 && cid < nrows) {
            const float4* b4 = (const float4*)(bank + (long long)cid * KDIM);
            const float4* q4 = (const float4*)(g_qn + q * KDIM);
            float dot = 0.f, ss = 0.f;
            #pragma unroll
            for (int i = 0; i < 6; i++) {
                float4 bb = b4[lane + i * 32];
                float4 qq = q4[lane + i * 32];
                dot = fmaf(qq.x, bb.x, fmaf(qq.y, bb.y, fmaf(qq.z, bb.z, fmaf(qq.w, bb.w, dot))));
                ss  = fmaf(bb.x, bb.x, fmaf(bb.y, bb.y, fmaf(bb.z, bb.z, fmaf(bb.w, bb.w, ss))));
            }
            #pragma unroll
            for (int o = 16; o; o >>= 1) {
                dot += __shfl_xor_sync(0xffffffffu, dot, o);
                ss  += __shfl_xor_sync(0xffffffffu, ss,  o);
            }
            val = dot / fmaxf(sqrtf(ss), 1e-12f);
        }
        if (lane == 0) rv[c] = val;
    }
    __syncthreads();

    if (tid == 0) {
        bool used[CAND];
        #pragma unroll
        for (int i = 0; i < CAND; i++) used[i] = false;
        for (int j = 0; j < k; j++) {
            int best = -1; float bvv = -3.4e38f;
            for (int i = 0; i < CAND; i++) {
                if (used[i]) continue;
                if (best < 0 || rv[i] > bvv ||
                    (rv[i] == bvv && sid[i] < sid[best])) { bvv = rv[i]; best = i; }
            }
            used[best] = true;
            out[q * k + j]          = bvv;
            out[NQ * k + q * k + j] = (float)sid[best];
        }
    }
}

// ---------------- launch -----------------------------------------------------
extern "C" void kernel_launch(void* const* d_in, const int* in_sizes, int n_in,
                              void* d_out, int out_size) {
    const float* query = (const float*)d_in[0];
    const float* bank  = (const float*)d_in[1];
    const int nrows = in_sizes[1] / KDIM;
    const int k = out_size / (2 * NQ);

    cudaFuncSetAttribute(score_kernel, cudaFuncAttributeMaxDynamicSharedMemorySize, SCORE_SMEM);

    norm_q_kernel<<<NQ, 256>>>(query);

    const int ntiles = (nrows + TILE_M - 1) / TILE_M;
    score_kernel<<<ntiles, 256, SCORE_SMEM>>>(bank, nrows);

    merge_final_kernel<<<NQ, 256>>>(bank, (float*)d_out, nrows, k, ntiles);
}